// round 14
// baseline (speedup 1.0000x reference)
#include <cuda_runtime.h>
#include <cuda_fp16.h>
#include <math.h>
#include <stdint.h>

// ---------------- problem constants ----------------
#define BATCH 32
#define SEQ   257
#define DIM   1024
#define QKVD  3072
#define NHEAD 16
#define HDIM  64
#define NEXP  8
#define TOPK  2
#define RANK  16
#define GHID  256
#define SD    (SEQ*DIM)
#define MROWS (BATCH*SEQ)        // 8224
#define MBLK  65                 // ceil(8224/128)
#define ATTN_SCALE 0.125f
#define SCL2E 0.18033688011112042f   // ATTN_SCALE * log2(e)

// ---------------- static device scratch ----------------
__device__ int   g_idx[BATCH*TOPK];
__device__ float g_gates[BATCH*TOPK];
__device__ float g_pooled[BATCH*DIM];
__device__ float g_bcat[QKVD];
__device__ __align__(16) uint32_t g_xhp[(long)MBLK*32*2048];    // permuted x (A frag order)
__device__ __align__(16) uint32_t g_Wmp[(long)32*32*2048];      // permuted weights (B frag order)
__device__ __align__(16) uint32_t g_ctxp[(long)MBLK*32*2048];   // permuted ctx (zero-init padding)
__device__ __align__(16) __half g_Vw[(long)BATCH*128*DIM];      // [b][p*32+j][d]
__device__ __align__(16) __half g_Uw[4ll*BATCH*DIM*32];         // [p][b][n][j]
__device__ __align__(16) __half g_t [(long)BATCH*SEQ*96];       // qkv low-rank t [b][s][96]
__device__ __align__(16) __half g_t3[(long)BATCH*SEQ*32];       // o low-rank t
__device__ __align__(16) __half g_qkv[(long)(MROWS+32)*QKVD];
__device__ __align__(16) __half g_ctx[MROWS*DIM];

__device__ __forceinline__ uint32_t smem_u32(const void* p) {
    uint32_t a;
    asm("{ .reg .u64 t; cvta.to.shared.u64 t, %1; cvt.u32.u64 %0, t; }" : "=r"(a) : "l"(p));
    return a;
}
__device__ __forceinline__ void cp16(uint32_t saddr, const void* g) {
    asm volatile("cp.async.cg.shared.global [%0], [%1], 16;" :: "r"(saddr), "l"(g));
}

// permuted-ctx scatter: write half2 bits for (global row m, even col kz)
__device__ __forceinline__ void store_ctxp(uint32_t* __restrict__ cp, int m, int kz, uint32_t val)
{
    int mb = m >> 7, mrem = m & 127;
    int mt = mrem >> 4, w16 = mrem & 15;
    int g = w16 & 7, rh = w16 >> 3;
    int kc = kz >> 5, krem = kz & 31;
    int kk = krem >> 4, kin = krem & 15;
    int tg = (kin & 7) >> 1, kh = kin >> 3;
    long off = ((long)(mb*32 + kc)*512 + kk*256 + mt*32 + g*4 + tg)*4 + kh*2 + rh;
    cp[off] = val;
}

// ---------------- permutation kernels ----------------
__global__ void cvt_xp_kernel(const float* __restrict__ x, uint32_t* __restrict__ xp)
{
    long idx = (long)blockIdx.x * 256 + threadIdx.x;
    if (idx >= (long)MBLK*32*512) return;
    int q  = (int)(idx & 511);
    long r = idx >> 9;
    int kc = (int)(r & 31);
    int mb = (int)(r >> 5);
    int kk = q >> 8, mt = (q >> 5) & 7, lane = q & 31;
    int g = lane >> 2, tg = lane & 3;
    int mbase = mb*128 + mt*16 + g;
    int kbase = kc*32 + kk*16 + tg*2;
    uint32_t v[4];
    #pragma unroll
    for (int j = 0; j < 4; j++) {
        int kh = j >> 1, rh = j & 1;
        int m = mbase + rh*8;
        int kz = kbase + kh*8;
        half2 h2 = (m < MROWS)
            ? __floats2half2_rn(x[(long)m*DIM + kz], x[(long)m*DIM + kz + 1])
            : __floats2half2_rn(0.f, 0.f);
        v[j] = *reinterpret_cast<uint32_t*>(&h2);
    }
    *(uint4*)(xp + idx*4) = make_uint4(v[0], v[1], v[2], v[3]);
}

// weights -> permuted B-frag layout; tail blocks (>=2048) concat biases
__global__ void cvt4p_kernel(const float* __restrict__ w0, const float* __restrict__ w1,
                             const float* __restrict__ w2, const float* __restrict__ w3,
                             uint32_t* __restrict__ wp,
                             const float* __restrict__ b0, const float* __restrict__ b1,
                             const float* __restrict__ b2, float* __restrict__ bcat)
{
    if (blockIdx.x >= 2048) {
        int i = (blockIdx.x - 2048) * 256 + threadIdx.x;
        if (i < DIM) bcat[i] = b0[i];
        else if (i < 2*DIM) bcat[i] = b1[i - DIM];
        else if (i < 3*DIM) bcat[i] = b2[i - 2*DIM];
        return;
    }
    long idx = (long)blockIdx.x * 256 + threadIdx.x;
    int q  = (int)(idx & 511);
    long r = idx >> 9;
    int kc = (int)(r & 31);
    int nb = (int)(r >> 5);
    int kk = q >> 8, np = (q >> 5) & 7, lane = q & 31;
    int gc = lane >> 2, tg = lane & 3;
    int kbase = kc*32 + kk*16 + tg*2;
    uint32_t v[4];
    #pragma unroll
    for (int j = 0; j < 4; j++) {
        int sub = j >> 1, kh = j & 1;
        int n = nb*128 + np*16 + sub*8 + gc;
        int p = n >> 10, row = n & 1023;
        const float* w = (p == 0) ? w0 : (p == 1) ? w1 : (p == 2) ? w2 : w3;
        int kz = kbase + kh*8;
        half2 h2 = __floats2half2_rn(w[(long)row*DIM + kz], w[(long)row*DIM + kz + 1]);
        v[j] = *reinterpret_cast<uint32_t*>(&h2);
    }
    *(uint4*)(wp + idx*4) = make_uint4(v[0], v[1], v[2], v[3]);
}

// ---------------- pooling (fp32, exact) ----------------
__global__ void pool_kernel(const float* __restrict__ x, float* __restrict__ pooled)
{
    int b = blockIdx.y;
    int d = blockIdx.x * 128 + (threadIdx.x & 127);
    int half = threadIdx.x >> 7;
    const float* xb = x + (long)b*SD + d;
    int t0 = half * 129;
    int t1 = half ? SEQ : 129;
    float s = 0.f;
    for (int t = t0; t < t1; t++) s += xb[(long)t*DIM];
    __shared__ float red[256];
    red[threadIdx.x] = s;
    __syncthreads();
    if (half == 0)
        pooled[b*DIM + d] = (red[threadIdx.x] + red[threadIdx.x + 128]) * (1.0f / SEQ);
}

// ---------------- gating MLP (exact fp32, float4 loads) ----------------
__global__ void gating_kernel(const float* __restrict__ pooled,
                              const float* __restrict__ gw1, const float* __restrict__ gb1,
                              const float* __restrict__ gw2, const float* __restrict__ gb2,
                              int* __restrict__ idx, float* __restrict__ gates)
{
    int b = blockIdx.x;
    int tid = threadIdx.x;
    __shared__ float pl[DIM];
    __shared__ float h[GHID];
    __shared__ float logits[NEXP];

    for (int d = tid; d < DIM; d += 256) pl[d] = pooled[b*DIM + d];
    __syncthreads();
    {
        float s = gb1[tid];
        const float4* w4 = (const float4*)(gw1 + (long)tid * DIM);
        #pragma unroll 4
        for (int d = 0; d < DIM/4; d++) {
            float4 wv = w4[d];
            const float* pv = &pl[d*4];
            s += pv[0]*wv.x + pv[1]*wv.y + pv[2]*wv.z + pv[3]*wv.w;
        }
        h[tid] = fmaxf(s, 0.f);
    }
    __syncthreads();
    if (tid < NEXP) {
        float s = gb2[tid];
        const float* w = gw2 + (long)tid * GHID;
        for (int g = 0; g < GHID; g++) s += h[g] * w[g];
        logits[tid] = s;
    }
    __syncthreads();
    if (tid == 0) {
        int i1 = 0; float v1 = logits[0];
        for (int e = 1; e < NEXP; e++) if (logits[e] > v1) { v1 = logits[e]; i1 = e; }
        int i2 = -1; float v2 = -3.0e38f;
        for (int e = 0; e < NEXP; e++) if (e != i1 && logits[e] > v2) { v2 = logits[e]; i2 = e; }
        float e2 = expf(v2 - v1);
        float inv = 1.f / (1.f + e2);
        idx[b*2] = i1; idx[b*2+1] = i2;
        gates[b*2] = inv; gates[b*2+1] = e2 * inv;
    }
}

// ---------------- fused fold: Vw -> [b][p*32+j][d], Uw -> [p][b][n][j] ----------------
__global__ void build_uv_kernel(const float* __restrict__ U0, const float* __restrict__ U1,
                                const float* __restrict__ U2, const float* __restrict__ U3,
                                const float* __restrict__ S0, const float* __restrict__ S1,
                                const float* __restrict__ S2, const float* __restrict__ S3,
                                const float* __restrict__ V0, const float* __restrict__ V1,
                                const float* __restrict__ V2, const float* __restrict__ V3,
                                const int* __restrict__ idx, const float* __restrict__ gates,
                                __half* __restrict__ VwAll, __half* __restrict__ UwAll)
{
    int p = blockIdx.x >> 5, b = blockIdx.x & 31;
    const float* U = (p == 0) ? U0 : (p == 1) ? U1 : (p == 2) ? U2 : U3;
    const float* Sg = (p == 0) ? S0 : (p == 1) ? S1 : (p == 2) ? S2 : S3;
    const float* V = (p == 0) ? V0 : (p == 1) ? V1 : (p == 2) ? V2 : V3;
    int tid = threadIdx.x;
    int e0 = idx[b*2], e1 = idx[b*2+1];
    float g0 = gates[b*2], g1 = gates[b*2+1];
    __half* vw = VwAll + ((long)b*128 + p*32) * DIM;
    __half* uw = UwAll + ((long)p*BATCH + b) * DIM * 32;

    for (int i = tid; i < 32*DIM; i += 256) {
        int j = i >> 10, d = i & (DIM-1);
        int k = j >> 4, r = j & 15;
        int e = k ? e1 : e0;
        vw[i] = __float2half_rn(Sg[e*RANK + r] * V[((long)e*RANK + r)*DIM + d]);
    }
    for (int i = tid; i < DIM*32; i += 256) {
        int n = i >> 5, j = i & 31;
        int k = j >> 4, r = j & 15;
        int e = k ? e1 : e0;
        float g = k ? g1 : g0;
        uw[i] = __float2half_rn(g * U[((long)e*DIM + n)*RANK + r]);
    }
}

// ---------------- FP16 MMA primitive ----------------
__device__ __forceinline__ void mma_f16(float c[4], const uint32_t a[4], const uint32_t b0, const uint32_t b1) {
    asm volatile(
        "mma.sync.aligned.m16n8k16.row.col.f32.f16.f16.f32 "
        "{%0,%1,%2,%3}, {%4,%5,%6,%7}, {%8,%9}, {%0,%1,%2,%3};"
        : "+f"(c[0]), "+f"(c[1]), "+f"(c[2]), "+f"(c[3])
        : "r"(a[0]), "r"(a[1]), "r"(a[2]), "r"(a[3]), "r"(b0), "r"(b1));
}

__device__ __forceinline__ float2 ld2(const float* p)  { return *reinterpret_cast<const float2*>(p); }
__device__ __forceinline__ float2 ld2(const __half* p) { return __half22float2(*reinterpret_cast<const half2*>(p)); }
__device__ __forceinline__ void st2(float* p, float v0, float v1)  { *reinterpret_cast<float2*>(p) = make_float2(v0, v1); }
__device__ __forceinline__ void st2(__half* p, float v0, float v1) { *reinterpret_cast<half2*>(p) = __floats2half2_rn(v0, v1); }

__device__ __forceinline__ uint4 ldA8(const __half* p) { return *(const uint4*)p; }
__device__ __forceinline__ uint4 ldA8(const float* p) {
    float4 a = *(const float4*)p;
    float4 b = *(const float4*)(p + 4);
    half2 h0 = __floats2half2_rn(a.x, a.y);
    half2 h1 = __floats2half2_rn(a.z, a.w);
    half2 h2 = __floats2half2_rn(b.x, b.y);
    half2 h3 = __floats2half2_rn(b.z, b.w);
    return make_uint4(*reinterpret_cast<uint32_t*>(&h0), *reinterpret_cast<uint32_t*>(&h1),
                      *reinterpret_cast<uint32_t*>(&h2), *reinterpret_cast<uint32_t*>(&h3));
}

__device__ __forceinline__ uint32_t ex2_h2(float e0, float e1) {
    half2 h = __floats2half2_rn(e0, e1);
    uint32_t in = *reinterpret_cast<uint32_t*>(&h), r;
    asm("ex2.approx.f16x2 %0, %1;" : "=r"(r) : "r"(in));
    return r;
}

// ==================== WIDE FP16 GEMM: 2-chunk stages, 3-stage ring (96KB) ======
template<typename CT>
__global__ __launch_bounds__(256, 2)
void hgemm_wide2(const uint32_t* __restrict__ Ap, const uint32_t* __restrict__ Bp,
                 const float* __restrict__ bias, CT* __restrict__ C, int M, int ldc)
{
    extern __shared__ uint32_t sh[];
    uint32_t shb = smem_u32(sh);
    int tid = threadIdx.x;
    int warp = tid >> 5, lane = tid & 31;
    int mt0 = (warp & 3) * 2;
    int np0 = (warp >> 2) * 4;
    int g = lane >> 2, tg = lane & 3;
    int m0 = blockIdx.y * 128, n0 = blockIdx.x * 128;

    const uint32_t* Ar = Ap + (long)blockIdx.y * 32 * 2048;
    const uint32_t* Br = Bp + (long)blockIdx.x * 32 * 2048;

    float acc[2][8][4] = {};

    auto issue = [&](int pr) {
        uint32_t sbase = shb + (uint32_t)(pr % 3) * 32768;
        #pragma unroll
        for (int c = 0; c < 2; c++) {
            int kc = pr*2 + c;
            uint32_t d = sbase + c*16384u;
            const uint32_t* a = Ar + kc * 2048;
            const uint32_t* b = Br + kc * 2048;
            cp16(d +          tid*16, a + tid*4);
            cp16(d +  4096u + tid*16, a + 1024 + tid*4);
            cp16(d +  8192u + tid*16, b + tid*4);
            cp16(d + 12288u + tid*16, b + 1024 + tid*4);
        }
        asm volatile("cp.async.commit_group;");
    };

    issue(0);
    issue(1);

    for (int j = 0; j < 16; j++) {
        if (j < 15) asm volatile("cp.async.wait_group 1;");
        else        asm volatile("cp.async.wait_group 0;");
        __syncthreads();
        if (j + 2 < 16) issue(j + 2);

        uint32_t* stage = sh + (j % 3) * 8192;
        #pragma unroll
        for (int c = 0; c < 2; c++) {
            const uint32_t* As = stage + c*4096;
            const uint32_t* Bs = As + 2048;
            #pragma unroll
            for (int kk = 0; kk < 2; kk++) {
                uint4 a4[2];
                a4[0] = *(const uint4*)&As[((kk*8 + mt0    )*32 + lane)*4];
                a4[1] = *(const uint4*)&As[((kk*8 + mt0 + 1)*32 + lane)*4];
                uint4 bp[4];
                #pragma unroll
                for (int p = 0; p < 4; p++)
                    bp[p] = *(const uint4*)&Bs[((kk*8 + np0 + p)*32 + lane)*4];
                #pragma unroll
                for (int i = 0; i < 2; i++) {
                    uint32_t a[4] = { a4[i].x, a4[i].y, a4[i].z, a4[i].w };
                    #pragma unroll
                    for (int p = 0; p < 4; p++) {
                        mma_f16(acc[i][2*p    ], a, bp[p].x, bp[p].y);
                        mma_f16(acc[i][2*p + 1], a, bp[p].z, bp[p].w);
                    }
                }
            }
        }
    }

    #pragma unroll
    for (int i = 0; i < 2; i++) {
        #pragma unroll
        for (int rs = 0; rs < 2; rs++) {
            int gm = m0 + (mt0 + i)*16 + g + rs*8;
            if (gm >= M) continue;
            #pragma unroll
            for (int j = 0; j < 8; j++) {
                int gn = n0 + (np0*2 + j)*8 + tg*2;
                long off = (long)gm*ldc + gn;
                st2(&C[off], acc[i][j][rs*2+0] + bias[gn], acc[i][j][rs*2+1] + bias[gn+1]);
            }
        }
    }
}

// ==================== general batched FP16 GEMM (double-buffered, typed A) ==========
#define TBN 64
template<bool ACC, typename AT, typename CT>
__global__ __launch_bounds__(256, 2)
void hgemm(const AT* __restrict__ A, const __half* __restrict__ B,
           CT* __restrict__ C,
           int M, int N, int K, int lda, int ldb, int ldc,
           long sA1, long sA2, long sB1, long sB2, long sC1, long sC2, int zdiv)
{
    int z = blockIdx.z;
    long zq = z / zdiv, zr = z % zdiv;
    A += zq*sA1 + zr*sA2;
    B += zq*sB1 + zr*sB2;
    C += zq*sC1 + zr*sC2;

    int m0 = blockIdx.y * 128, n0 = blockIdx.x * TBN;
    __shared__ uint32_t As[2][2048];
    __shared__ uint32_t Bs[2][1024];

    int tid = threadIdx.x;
    int warp = tid >> 5, lane = tid & 31;
    int mt0 = (warp & 3) * 2;
    int np0 = (warp >> 2) * 2;
    int g = lane >> 2, tg = lane & 3;

    float acc[2][4][4] = {};
    uint4 ar[2], br;

    const int KB = K / 32;

    auto load_regs = [&](int kb) {
        int k0 = kb * 32;
        #pragma unroll
        for (int i = 0; i < 2; i++) {
            int f4 = i*256 + tid;
            int row = f4 >> 2, c8 = f4 & 3;
            int gm = m0 + row;
            ar[i] = (gm < M) ? ldA8(A + (long)gm*lda + k0 + c8*8)
                             : make_uint4(0u,0u,0u,0u);
        }
        {
            int n = tid >> 2, c8 = tid & 3;
            int gn = n0 + n;
            br = (gn < N) ? *(const uint4*)(B + (long)gn*ldb + k0 + c8*8)
                          : make_uint4(0u,0u,0u,0u);
        }
    };

    auto sts = [&](int s) {
        #pragma unroll
        for (int i = 0; i < 2; i++) {
            int f4 = i*256 + tid;
            int row = f4 >> 2, c8 = f4 & 3;
            int kk = c8 >> 1, kh = c8 & 1;
            int mt = row >> 4, w = row & 15, gg = w & 7, rh = w >> 3;
            int base = ((kk*8 + mt)*32 + gg*4)*4 + kh*2 + rh;
            As[s][base +  0] = ar[i].x;
            As[s][base +  4] = ar[i].y;
            As[s][base +  8] = ar[i].z;
            As[s][base + 12] = ar[i].w;
        }
        {
            int n = tid >> 2, c8 = tid & 3;
            int kk = c8 >> 1, kh = c8 & 1;
            int nt = n >> 3, gc = n & 7, np = nt >> 1, sub = nt & 1;
            int base = ((kk*4 + np)*32 + gc*4)*4 + sub*2 + kh;
            Bs[s][base +  0] = br.x;
            Bs[s][base +  4] = br.y;
            Bs[s][base +  8] = br.z;
            Bs[s][base + 12] = br.w;
        }
    };

    load_regs(0);
    sts(0);
    __syncthreads();

    for (int kb = 0; kb < KB; kb++) {
        int s = kb & 1;
        if (kb + 1 < KB) load_regs(kb + 1);

        #pragma unroll
        for (int kk = 0; kk < 2; kk++) {
            uint4 a4[2];
            a4[0] = *(const uint4*)&As[s][((kk*8 + mt0    )*32 + lane)*4];
            a4[1] = *(const uint4*)&As[s][((kk*8 + mt0 + 1)*32 + lane)*4];
            uint4 bp[2];
            bp[0] = *(const uint4*)&Bs[s][((kk*4 + np0    )*32 + lane)*4];
            bp[1] = *(const uint4*)&Bs[s][((kk*4 + np0 + 1)*32 + lane)*4];
            #pragma unroll
            for (int i = 0; i < 2; i++) {
                uint32_t a[4] = { a4[i].x, a4[i].y, a4[i].z, a4[i].w };
                #pragma unroll
                for (int p = 0; p < 2; p++) {
                    mma_f16(acc[i][2*p    ], a, bp[p].x, bp[p].y);
                    mma_f16(acc[i][2*p + 1], a, bp[p].z, bp[p].w);
                }
            }
        }

        if (kb + 1 < KB) {
            sts(s ^ 1);
            __syncthreads();
        }
    }

    #pragma unroll
    for (int i = 0; i < 2; i++) {
        #pragma unroll
        for (int rs = 0; rs < 2; rs++) {
            int gm = m0 + (mt0 + i)*16 + g + rs*8;
            if (gm >= M) continue;
            #pragma unroll
            for (int j = 0; j < 4; j++) {
                int gn = n0 + (np0*2 + j)*8 + tg*2;
                if (gn >= N) continue;
                long off = (long)gm*ldc + gn;
                float v0 = acc[i][j][rs*2+0];
                float v1 = acc[i][j][rs*2+1];
                if (ACC) { float2 c2 = ld2(&C[off]); v0 += c2.x; v1 += c2.y; }
                st2(&C[off], v0, v1);
            }
        }
    }
}

// ==================== FLASH ATTENTION: one 512-thread CTA per (b,h), rows 0..255 ====
__global__ __launch_bounds__(512)
void flash_kernel(const __half* __restrict__ qkv, __half* __restrict__ ctx,
                  uint32_t* __restrict__ ctxp)
{
    __shared__ uint32_t ks[2048];
    __shared__ uint32_t vs[2048];
    __shared__ uint32_t ps[8192];   // [kk4][warp16][lane32][4]

    int tid = threadIdx.x, warp = tid >> 5, lane = tid & 31;
    int g = lane >> 2, tg = lane & 3;
    int bh = blockIdx.x;
    int b = bh >> 4, h = bh & 15;

    const __half* qb = qkv + (long)b*SEQ*QKVD + h*HDIM;
    const __half* kb = qkv + (long)b*SEQ*QKVD + DIM + h*HDIM;
    const __half* vb = qkv + (long)b*SEQ*QKVD + 2*DIM + h*HDIM;

    int r0 = warp*16 + g;      // 0..247
    int r1 = r0 + 8;           // <= 255

    uint32_t qa[4][4];
    #pragma unroll
    for (int kk = 0; kk < 4; kk++) {
        qa[kk][0] = *(const uint32_t*)(qb + (long)r0*QKVD + kk*16 + 2*tg);
        qa[kk][1] = *(const uint32_t*)(qb + (long)r1*QKVD + kk*16 + 2*tg);
        qa[kk][2] = *(const uint32_t*)(qb + (long)r0*QKVD + kk*16 + 8 + 2*tg);
        qa[kk][3] = *(const uint32_t*)(qb + (long)r1*QKVD + kk*16 + 8 + 2*tg);
    }

    float o[8][4] = {};
    float m0r = -1e30f, m1r = -1e30f, l0r = 0.f, l1r = 0.f;

    for (int j = 0; j < 5; j++) {
        int kv0 = j * 64;
        // K tile: 512 items, one per thread
        {
            int n = tid >> 3, c8 = tid & 7;
            int gr = kv0 + n;
            uint4 v = (gr < SEQ) ? *(const uint4*)(kb + (long)gr*QKVD + c8*8)
                                 : make_uint4(0u,0u,0u,0u);
            int kk = c8 >> 1, kh = c8 & 1;
            int nt = n >> 3, gc = n & 7;
            int base = ((kk*8 + nt)*32 + gc*4)*2 + kh;
            ks[base + 0] = v.x;
            ks[base + 2] = v.y;
            ks[base + 4] = v.z;
            ks[base + 6] = v.w;
        }
        // V tile: 256 items on threads 0..255
        if (tid < 256) {
            int kvpair = tid >> 3, nt = tid & 7;
            int rA = kv0 + kvpair*2, rB = rA + 1;
            union { uint4 u; __half hx[8]; } ua, ub;
            ua.u = (rA < SEQ) ? *(const uint4*)(vb + (long)rA*QKVD + nt*8) : make_uint4(0u,0u,0u,0u);
            ub.u = (rB < SEQ) ? *(const uint4*)(vb + (long)rB*QKVD + nt*8) : make_uint4(0u,0u,0u,0u);
            int klocal = kvpair*2;
            int kk = klocal >> 4, kin = klocal & 15;
            int kh = kin >> 3, t = (kin & 7) >> 1;
            #pragma unroll
            for (int jj = 0; jj < 8; jj++) {
                half2 h2 = __halves2half2(ua.hx[jj], ub.hx[jj]);
                vs[((kk*8 + nt)*32 + jj*4 + t)*2 + kh] = *reinterpret_cast<uint32_t*>(&h2);
            }
        }
        __syncthreads();

        float s[8][4] = {};
        #pragma unroll
        for (int kk = 0; kk < 4; kk++) {
            #pragma unroll
            for (int nt = 0; nt < 8; nt++) {
                uint2 bb = *(const uint2*)&ks[((kk*8 + nt)*32 + lane)*2];
                mma_f16(s[nt], qa[kk], bb.x, bb.y);
            }
        }

        float tmax0 = -1e30f, tmax1 = -1e30f;
        if (j < 4) {
            #pragma unroll
            for (int nt = 0; nt < 8; nt++) {
                tmax0 = fmaxf(tmax0, fmaxf(s[nt][0], s[nt][1]));
                tmax1 = fmaxf(tmax1, fmaxf(s[nt][2], s[nt][3]));
            }
        } else {
            #pragma unroll
            for (int nt = 0; nt < 8; nt++) {
                int c0 = kv0 + nt*8 + 2*tg;
                if (c0     >= SEQ) { s[nt][0] = -1e30f; s[nt][2] = -1e30f; }
                if (c0 + 1 >= SEQ) { s[nt][1] = -1e30f; s[nt][3] = -1e30f; }
                tmax0 = fmaxf(tmax0, fmaxf(s[nt][0], s[nt][1]));
                tmax1 = fmaxf(tmax1, fmaxf(s[nt][2], s[nt][3]));
            }
        }
        tmax0 = fmaxf(tmax0, __shfl_xor_sync(0xffffffffu, tmax0, 1));
        tmax0 = fmaxf(tmax0, __shfl_xor_sync(0xffffffffu, tmax0, 2));
        tmax1 = fmaxf(tmax1, __shfl_xor_sync(0xffffffffu, tmax1, 1));
        tmax1 = fmaxf(tmax1, __shfl_xor_sync(0xffffffffu, tmax1, 2));
        float nm0 = fmaxf(m0r, tmax0), nm1 = fmaxf(m1r, tmax1);
        float f0 = exp2f((m0r - nm0)*SCL2E), f1 = exp2f((m1r - nm1)*SCL2E);

        float sum0 = 0.f, sum1 = 0.f;
        #pragma unroll
        for (int nt = 0; nt < 8; nt++) {
            uint32_t r01 = ex2_h2((s[nt][0] - nm0)*SCL2E, (s[nt][1] - nm0)*SCL2E);
            uint32_t r23 = ex2_h2((s[nt][2] - nm1)*SCL2E, (s[nt][3] - nm1)*SCL2E);
            float2 f01 = __half22float2(*reinterpret_cast<half2*>(&r01));
            float2 f23 = __half22float2(*reinterpret_cast<half2*>(&r23));
            sum0 += f01.x + f01.y;
            sum1 += f23.x + f23.y;
            int kkp = nt >> 1, kh = nt & 1;
            int base = ((kkp*16 + warp)*32 + lane)*4 + kh*2;
            ps[base + 0] = r01;
            ps[base + 1] = r23;
        }
        sum0 += __shfl_xor_sync(0xffffffffu, sum0, 1);
        sum0 += __shfl_xor_sync(0xffffffffu, sum0, 2);
        sum1 += __shfl_xor_sync(0xffffffffu, sum1, 1);
        sum1 += __shfl_xor_sync(0xffffffffu, sum1, 2);
        l0r = l0r*f0 + sum0;
        l1r = l1r*f1 + sum1;
        m0r = nm0; m1r = nm1;
        #pragma unroll
        for (int nt = 0; nt < 8; nt++) {
            o[nt][0] *= f0; o[nt][1] *= f0;
            o[nt][2] *= f1; o[nt][3] *= f1;
        }

        #pragma unroll
        for (int kk = 0; kk < 4; kk++) {
            uint4 p4 = *(const uint4*)&ps[((kk*16 + warp)*32 + lane)*4];
            uint32_t pa[4] = { p4.x, p4.y, p4.z, p4.w };
            #pragma unroll
            for (int nt = 0; nt < 8; nt++) {
                uint2 vv = *(const uint2*)&vs[((kk*8 + nt)*32 + lane)*2];
                mma_f16(o[nt], pa, vv.x, vv.y);
            }
        }
        __syncthreads();
    }

    float inv0 = 1.f / l0r, inv1 = 1.f / l1r;
    __half* cb = ctx + (long)b*SEQ*DIM + h*HDIM;
    int gm0 = b*SEQ + r0, gm1 = b*SEQ + r1;
    #pragma unroll
    for (int nt = 0; nt < 8; nt++) {
        int col = nt*8 + 2*tg;
        half2 h2a = __floats2half2_rn(o[nt][0]*inv0, o[nt][1]*inv0);
        *reinterpret_cast<half2*>(cb + (long)r0*DIM + col) = h2a;
        store_ctxp(ctxp, gm0, h*HDIM + col, *reinterpret_cast<uint32_t*>(&h2a));
        half2 h2b = __floats2half2_rn(o[nt][2]*inv1, o[nt][3]*inv1);
        *reinterpret_cast<half2*>(cb + (long)r1*DIM + col) = h2b;
        store_ctxp(ctxp, gm1, h*HDIM + col, *reinterpret_cast<uint32_t*>(&h2b));
    }
}

// ---------------- attention tail: q-row 256 (writes ctx + ctxp) ----------------
__global__ __launch_bounds__(256)
void attn_tail_kernel(const __half* __restrict__ qkv, __half* __restrict__ ctx,
                      uint32_t* __restrict__ ctxp)
{
    int bh = blockIdx.x;
    int b = bh >> 4, h = bh & 15;
    const __half* qb = qkv + (long)b*SEQ*QKVD + 256l*QKVD + h*HDIM;
    const __half* kb = qkv + (long)b*SEQ*QKVD + DIM + h*HDIM;
    const __half* vb = qkv + (long)b*SEQ*QKVD + 2*DIM + h*HDIM;
    int tid = threadIdx.x;

    __shared__ float q[HDIM];
    __shared__ float sc[SEQ];
    __shared__ float red[256];

    if (tid < HDIM) q[tid] = __half2float(qb[tid]);
    __syncthreads();

    for (int j = tid; j < SEQ; j += 256) {
        const half2* kr = (const half2*)(kb + (long)j*QKVD);
        float s = 0.f;
        #pragma unroll
        for (int d = 0; d < HDIM/2; d++) {
            float2 kv = __half22float2(kr[d]);
            s += q[d*2]*kv.x + q[d*2+1]*kv.y;
        }
        sc[j] = s * ATTN_SCALE;
    }
    __syncthreads();

    float m = -3.0e38f;
    for (int j = tid; j < SEQ; j += 256) m = fmaxf(m, sc[j]);
    red[tid] = m; __syncthreads();
    for (int s = 128; s > 0; s >>= 1) { if (tid < s) red[tid] = fmaxf(red[tid], red[tid+s]); __syncthreads(); }
    m = red[0]; __syncthreads();

    float sum = 0.f;
    for (int j = tid; j < SEQ; j += 256) { float e = __expf(sc[j] - m); sc[j] = e; sum += e; }
    red[tid] = sum; __syncthreads();
    for (int s = 128; s > 0; s >>= 1) { if (tid < s) red[tid] += red[tid+s]; __syncthreads(); }
    float inv = 1.f / red[0];
    __syncthreads();

    int d = tid & 63, grp = tid >> 6;
    float acc = 0.f;
    for (int j = grp; j < SEQ; j += 4)
        acc += sc[j] * __half2float(vb[(long)j*QKVD + d]);
    red[tid] = acc; __syncthreads();
    if (grp == 0) {
        float o = (red[d] + red[64+d] + red[128+d] + red[192+d]) * inv;
        ctx[(long)b*SEQ*DIM + 256l*DIM + h*HDIM + d] = __float2half_rn(o);
        float o2 = __shfl_down_sync(0xffffffffu, o, 1);
        if ((d & 1) == 0) {
            half2 hv = __floats2half2_rn(o, o2);
            store_ctxp(ctxp, b*SEQ + 256, h*HDIM + d, *reinterpret_cast<uint32_t*>(&hv));
        }
    }
}

// ---------------- host launch ----------------
static void* dsym(const void* symbol) { void* p = nullptr; cudaGetSymbolAddress(&p, symbol); return p; }
static inline dim3 hgrid(int N, int M, int Z) { return dim3((N+TBN-1)/TBN, (M+127)/128, Z); }
#define WIDE2_SMEM 98304

extern "C" void kernel_launch(void* const* d_in, const int* in_sizes, int n_in,
                              void* d_out, int out_size)
{
    const float* x   = (const float*)d_in[0];
    const float* gw1 = (const float*)d_in[1];
    const float* gb1 = (const float*)d_in[2];
    const float* gw2 = (const float*)d_in[3];
    const float* gb2 = (const float*)d_in[4];
    const float* Wm[4]; const float* Ue[4]; const float* Se[4]; const float* Ve[4]; const float* bi[4];
    for (int p = 0; p < 4; p++) {
        Wm[p] = (const float*)d_in[5 + p*5 + 0];
        Ue[p] = (const float*)d_in[5 + p*5 + 1];
        Se[p] = (const float*)d_in[5 + p*5 + 2];
        Ve[p] = (const float*)d_in[5 + p*5 + 3];
        bi[p] = (const float*)d_in[5 + p*5 + 4];
    }
    float* out = (float*)d_out;

    int*      idxp   = (int*)dsym(g_idx);
    float*    gatesp = (float*)dsym(g_gates);
    float*    pooled = (float*)dsym(g_pooled);
    float*    bcat   = (float*)dsym(g_bcat);
    uint32_t* xhp    = (uint32_t*)dsym(g_xhp);
    uint32_t* Wmp    = (uint32_t*)dsym(g_Wmp);
    uint32_t* ctxp   = (uint32_t*)dsym(g_ctxp);
    __half*   Vw     = (__half*)dsym(g_Vw);
    __half*   Uw     = (__half*)dsym(g_Uw);
    __half*   tbuf   = (__half*)dsym(g_t);
    __half*   t3     = (__half*)dsym(g_t3);
    __half*   qkv    = (__half*)dsym(g_qkv);
    __half*   ctx    = (__half*)dsym(g_ctx);

    const long UW_PER = (long)BATCH*DIM*32;

    cudaFuncSetAttribute(hgemm_wide2<__half>, cudaFuncAttributeMaxDynamicSharedMemorySize, WIDE2_SMEM);
    cudaFuncSetAttribute(hgemm_wide2<float>,  cudaFuncAttributeMaxDynamicSharedMemorySize, WIDE2_SMEM);

    // 0..1: dependencies of the wide QKV GEMM (cvt4p tail blocks do bias concat)
    cvt_xp_kernel<<<(MBLK*32*512 + 255)/256, 256>>>(x, xhp);                       // 0
    cvt4p_kernel<<<2060, 256>>>(Wm[0], Wm[1], Wm[2], Wm[3], Wmp,
                                bi[0], bi[1], bi[2], bcat);                        // 1

    // 2: fused main projection
    hgemm_wide2<__half><<<dim3(QKVD/128, MBLK), 256, WIDE2_SMEM>>>(
        xhp, Wmp, bcat, qkv, MROWS, QKVD);

    // 3..5: gating path + expert folding
    pool_kernel<<<dim3(8, BATCH), 256>>>(x, pooled);                               // 3
    gating_kernel<<<BATCH, 256>>>(pooled, gw1, gb1, gw2, gb2, idxp, gatesp);       // 4
    build_uv_kernel<<<128, 256>>>(Ue[0], Ue[1], Ue[2], Ue[3],
                                  Se[0], Se[1], Se[2], Se[3],
                                  Ve[0], Ve[1], Ve[2], Ve[3],
                                  idxp, gatesp, Vw, Uw);                           // 5

    // 6: fused xV for q,k,v (reads fp32 x directly): t[b] = x_b @ Vw_b[0:96]^T
    hgemm<false, float, __half><<<hgrid(96, SEQ, BATCH), 256>>>(
        x, Vw, tbuf,
        SEQ, 96, DIM, DIM, DIM, 96,
        0, (long)SD, 0, (long)128*DIM, 0, (long)SEQ*96, BATCH);

    // 7: fused expert accumulate: qkv[:, p*1024 + n] += t[:, p*32:(p+1)*32] @ Uw_p^T
    hgemm<true, __half, __half><<<hgrid(DIM, SEQ, 3*BATCH), 256>>>(
        tbuf, Uw, qkv,
        SEQ, DIM, 32, 96, 32, QKVD,
        32, (long)SEQ*96, UW_PER, (long)DIM*32, (long)DIM, (long)SEQ*QKVD, BATCH);

    // 8: flash attention (512-thread CTA per (b,h)) + 9: tail row 256
    flash_kernel<<<BATCH*NHEAD, 512>>>(qkv, ctx, ctxp);
    attn_tail_kernel<<<BATCH*NHEAD, 256>>>(qkv, ctx, ctxp);

    // 10: ctx low-rank projection: t3[b] = ctx_b @ Vw_b[96:128]^T
    hgemm<false, __half, __half><<<hgrid(32, SEQ, BATCH), 256>>>(
        ctx, Vw + 96*DIM, t3,
        SEQ, 32, DIM, DIM, DIM, 32,
        0, (long)SD, 0, (long)128*DIM, 0, (long)SEQ*32, BATCH);

    // 11: out = ctx @ Wo^T + bo (fp32 out; ctxp written by flash/tail)
    hgemm_wide2<float><<<dim3(DIM/128, MBLK), 256, WIDE2_SMEM>>>(
        ctxp, Wmp + (long)24*32*2048, bi[3], out, MROWS, DIM);

    // 12: out += t3 @ Uw3^T (fp32 accumulate)
    hgemm<true, __half, float><<<hgrid(DIM, SEQ, BATCH), 256>>>(
        t3, Uw + 3*UW_PER, out,
        SEQ, DIM, 32, 32, 32, DIM,
        0, (long)SEQ*32, 0, (long)DIM*32, 0, (long)SD, BATCH);
}